// round 9
// baseline (speedup 1.0000x reference)
#include <cuda_runtime.h>
#include <cuda_fp16.h>
#include <math_constants.h>
#include <cstdint>

#define Bn 128
#define Hn 128

__device__ float    g_scores[Bn * Bn];
__device__ unsigned g_cnt = 0;
// Fragment-major fp16 operand storage (written by convert pre-kernel):
//  Q: [mtile16 0..255][ks 0..7][lane 0..31][16B]   (A fragments, m16k16)
//  P: [c 0..127][ks 0..7][blk 0..7][lane 0..31][16B] (B fragments, n16k16)
__device__ __align__(16) char g_Qh[256 * 8 * 512];        // 1MB
__device__ __align__(16) char g_Ph[128 * 8 * 8 * 512];    // 4MB
// Deferred per-warp row-max scratch: [cta][c][wn][64]
__device__ __align__(16) float g_rmax[256 * 32 * 2 * 64];

__device__ __forceinline__ uint32_t pack2(float a, float b) {
    __half2 h = __floats2half2_rn(a, b);
    return *reinterpret_cast<uint32_t*>(&h);
}
__device__ __forceinline__ void mma16(float* d, const uint32_t* a, uint32_t b0, uint32_t b1) {
    asm volatile(
        "mma.sync.aligned.m16n8k16.row.col.f32.f16.f16.f32 "
        "{%0,%1,%2,%3}, {%4,%5,%6,%7}, {%8,%9}, {%0,%1,%2,%3};"
        : "+f"(d[0]), "+f"(d[1]), "+f"(d[2]), "+f"(d[3])
        : "r"(a[0]), "r"(a[1]), "r"(a[2]), "r"(a[3]), "r"(b0), "r"(b1));
}

// ---------------------------------------------------------------------------
// Convert: fp32 inputs -> fragment-major fp16.
// mma.m16n8k16 fragment layouts (lane l, 4 regs = 16B):
//  A: a0=(r, k..k+1) a1=(r+8, k) a2=(r, k+8) a3=(r+8, k+8); r=l/4, k=2*(l%4)
//  B: b0=(n, k..k+1) b1=(n, k+8) b2=(n+8, k) b3=(n+8, k+8); n=l/4
// Blocks 0..127: P tile c=bid. Blocks 128..159: Q rows (bid-128)*128.
// ---------------------------------------------------------------------------
extern "C" __global__ void __launch_bounds__(256)
colbert_convert(const float* __restrict__ Q, const float* __restrict__ P)
{
    const int bid = blockIdx.x, t = threadIdx.x;
    if (bid < 128) {
        const float* Pb = P + (size_t)bid * 16384;
        char* dst = g_Ph + (size_t)bid * 32768;
        #pragma unroll
        for (int j = 0; j < 8; ++j) {
            int q = j * 256 + t;                 // 0..2047
            int ks   = q >> 8;
            int blk  = (q >> 5) & 7;
            int lane = q & 31;
            int n = blk * 16 + (lane >> 2);
            int k = ks * 16 + 2 * (lane & 3);
            const float* r0 = Pb + n * 128 + k;
            const float* r1 = Pb + (n + 8) * 128 + k;
            uint4 w;
            w.x = pack2(r0[0], r0[1]);
            w.y = pack2(r0[8], r0[9]);
            w.z = pack2(r1[0], r1[1]);
            w.w = pack2(r1[8], r1[9]);
            *reinterpret_cast<uint4*>(dst + q * 16) = w;
        }
    } else {
        const int qi = bid - 128;                // 0..31
        char* dst = g_Qh + (size_t)qi * 32768;
        #pragma unroll
        for (int j = 0; j < 8; ++j) {
            int q = j * 256 + t;
            int mt_l = q >> 8;                   // mtile within this 128-row group
            int ks   = (q >> 5) & 7;
            int lane = q & 31;
            int r = (qi * 8 + mt_l) * 16 + (lane >> 2);
            int k = ks * 16 + 2 * (lane & 3);
            const float* r0 = Q + (size_t)r * 128 + k;
            const float* r1 = Q + (size_t)(r + 8) * 128 + k;
            uint4 w;
            w.x = pack2(r0[0], r0[1]);
            w.y = pack2(r1[0], r1[1]);
            w.z = pack2(r0[8], r0[9]);
            w.w = pack2(r1[8], r1[9]);
            *reinterpret_cast<uint4*>(dst + q * 16) = w;
        }
    }
}

// ---------------------------------------------------------------------------
// Main: 256 CTAs x 128 threads, 2 CTAs/SM, ZERO smem in the mainloop.
// CTA (mi2=bid>>2: rows [mi2*64,+64), cg=bid&3). Warps: wm=wid>>1, wn=wid&1.
// B fragments LDG'd straight from L1/L2 with a depth-4 register ring,
// prefetch distance 2 k-steps. No barriers until after the loop.
// ---------------------------------------------------------------------------
extern "C" __global__ void __launch_bounds__(128, 2)
colbert_fused(float* __restrict__ out)
{
    const int t    = threadIdx.x;
    const int lane = t & 31;
    const int wid  = t >> 5;
    const int wm   = wid >> 1;
    const int wn   = wid & 1;
    const int mi2  = blockIdx.x >> 2;
    const int cg   = blockIdx.x & 3;
    const int gid  = lane >> 2;
    const int tig  = lane & 3;

    // ---- A fragments (register-resident all 32 c's)
    uint32_t aF[2][8][4];
    {
        const char* gA = g_Qh + ((size_t)(mi2 * 4 + wm * 2) * 8) * 512 + (size_t)lane * 16;
        #pragma unroll
        for (int mt = 0; mt < 2; ++mt)
            #pragma unroll
            for (int ks = 0; ks < 8; ++ks) {
                uint4 v = __ldg(reinterpret_cast<const uint4*>(gA + (mt * 8 + ks) * 512));
                aF[mt][ks][0] = v.x; aF[mt][ks][1] = v.y;
                aF[mt][ks][2] = v.z; aF[mt][ks][3] = v.w;
            }
    }

    // ---- B fragment stream: step u = i*8+ks reads pB + u*4096 + np*512
    const char* pB = g_Ph + (size_t)(cg * 32) * 32768 + (size_t)(wn * 4) * 512 + (size_t)lane * 16;

    uint32_t bF[4][4][4];     // ring slot = ks&3 (8%4==0 keeps it static)
    #pragma unroll
    for (int u = 0; u < 2; ++u)
        #pragma unroll
        for (int np = 0; np < 4; ++np) {
            uint4 v = __ldg(reinterpret_cast<const uint4*>(pB + u * 4096 + np * 512));
            bF[u][np][0] = v.x; bF[u][np][1] = v.y;
            bF[u][np][2] = v.z; bF[u][np][3] = v.w;
        }
    const char* pPre = pB + 2 * 4096;

    for (int i = 0; i < 32; ++i) {
        float acc[2][8][4];
        #pragma unroll
        for (int mt = 0; mt < 2; ++mt)
            #pragma unroll
            for (int nt = 0; nt < 8; ++nt)
                #pragma unroll
                for (int r = 0; r < 4; ++r) acc[mt][nt][r] = 0.0f;

        #pragma unroll
        for (int ks = 0; ks < 8; ++ks) {
            // prefetch step u+2 into slot (ks+2)&3
            if (i * 8 + ks + 2 < 256) {
                const int ps = (ks + 2) & 3;
                #pragma unroll
                for (int np = 0; np < 4; ++np) {
                    uint4 v = __ldg(reinterpret_cast<const uint4*>(pPre + np * 512));
                    bF[ps][np][0] = v.x; bF[ps][np][1] = v.y;
                    bF[ps][np][2] = v.z; bF[ps][np][3] = v.w;
                }
                pPre += 4096;
            }
            const int cs = ks & 3;
            #pragma unroll
            for (int np = 0; np < 4; ++np)
                #pragma unroll
                for (int mt = 0; mt < 2; ++mt) {
                    mma16(acc[mt][2 * np],     aF[mt][ks], bF[cs][np][0], bF[cs][np][1]);
                    mma16(acc[mt][2 * np + 1], aF[mt][ks], bF[cs][np][2], bF[cs][np][3]);
                }
        }

        // ---- epilogue: per-row max over this warp's 64 n-cols -> global scratch
        float* gr = g_rmax + ((size_t)(blockIdx.x * 32 + i) * 2 + wn) * 64;
        #pragma unroll
        for (int mt = 0; mt < 2; ++mt) {
            float m0 = acc[mt][0][0], m1 = acc[mt][0][2];
            #pragma unroll
            for (int nt = 0; nt < 8; ++nt) {
                m0 = fmaxf(m0, fmaxf(acc[mt][nt][0], acc[mt][nt][1]));
                m1 = fmaxf(m1, fmaxf(acc[mt][nt][2], acc[mt][nt][3]));
            }
            m0 = fmaxf(m0, __shfl_xor_sync(0xffffffffu, m0, 1));
            m0 = fmaxf(m0, __shfl_xor_sync(0xffffffffu, m0, 2));
            m1 = fmaxf(m1, __shfl_xor_sync(0xffffffffu, m1, 1));
            m1 = fmaxf(m1, __shfl_xor_sync(0xffffffffu, m1, 2));
            if (tig == 0) {
                gr[wm * 32 + mt * 16 + gid]     = m0;
                gr[wm * 32 + mt * 16 + 8 + gid] = m1;
            }
        }
    }

    __syncthreads();  // CTA-scope fence: all warps' g_rmax writes visible

    // ---- combine: warp w handles 8 c's; lane = s-row within each b
    {
        const int b0 = mi2 * 2, b1 = mi2 * 2 + 1;
        #pragma unroll
        for (int cl = 0; cl < 8; ++cl) {
            const int ci = wid * 8 + cl;
            const float* r = g_rmax + (size_t)(blockIdx.x * 32 + ci) * 128;
            float v0 = fmaxf(r[lane],      r[64 + lane]);
            float v1 = fmaxf(r[32 + lane], r[96 + lane]);
            #pragma unroll
            for (int off = 16; off; off >>= 1) {
                v0 += __shfl_xor_sync(0xffffffffu, v0, off);
                v1 += __shfl_xor_sync(0xffffffffu, v1, off);
            }
            if (lane == 0) {
                const int c = cg * 32 + ci;
                g_scores[b0 * Bn + c] = v0;
                g_scores[b1 * Bn + c] = v1;
            }
        }
    }

    // ---- last CTA computes the loss
    __syncthreads();
    __threadfence();
    __shared__ unsigned s_rank;
    __shared__ float sred[32];
    if (t == 0) s_rank = atomicAdd(&g_cnt, 1);
    __syncthreads();
    if (s_rank != 255) return;
    if (t == 0) atomicExch(&g_cnt, 0);
    __threadfence();

    const float4* rp = reinterpret_cast<const float4*>(&g_scores[t * Bn]);
    float m = -CUDART_INF_F, diag = 0.0f;
    #pragma unroll
    for (int k4 = 0; k4 < 32; ++k4) {
        float4 v = rp[k4];
        m = fmaxf(m, fmaxf(fmaxf(v.x, v.y), fmaxf(v.z, v.w)));
        int cb = k4 * 4;
        if (t == cb + 0) diag = v.x;
        if (t == cb + 1) diag = v.y;
        if (t == cb + 2) diag = v.z;
        if (t == cb + 3) diag = v.w;
    }
    float s = 0.0f;
    #pragma unroll
    for (int k4 = 0; k4 < 32; ++k4) {
        float4 v = rp[k4];
        s += expf(50.0f * (v.x - m)) + expf(50.0f * (v.y - m)) +
             expf(50.0f * (v.z - m)) + expf(50.0f * (v.w - m));
    }
    float term = 50.0f * diag - (50.0f * m + logf(s));

    #pragma unroll
    for (int off = 16; off; off >>= 1) term += __shfl_xor_sync(0xffffffffu, term, off);
    if (lane == 0) sred[wid] = term;
    __syncthreads();
    if (t == 0) out[0] = -(sred[0] + sred[1] + sred[2] + sred[3]) / 128.0f;
}

// ---------------------------------------------------------------------------
extern "C" void kernel_launch(void* const* d_in, const int* in_sizes, int n_in,
                              void* d_out, int out_size)
{
    const float* Q = (const float*)d_in[0];  // [128, 32, 128]
    const float* P = (const float*)d_in[1];  // [128, 128, 128]
    float* out = (float*)d_out;

    colbert_convert<<<160, 256>>>(Q, P);
    colbert_fused<<<256, 128>>>(out);
}

// round 10
// speedup vs baseline: 1.4669x; 1.4669x over previous
#include <cuda_runtime.h>
#include <cuda_fp16.h>
#include <math_constants.h>
#include <cstdint>

#define Bn 128
#define Hn 128

__device__ float    g_scores[Bn * Bn];
__device__ unsigned g_cnt = 0;
// Pre-converted, pre-swizzled fp16 tiles (tile = 128 rows x 256B swizzled;
// halves of 64 rows are the contiguous 16KB chunks)
__device__ __align__(16) char g_Qh[32 * 32768];    // 1MB: 32 Q tiles
__device__ __align__(16) char g_Ph[128 * 32768];   // 4MB: 128 P tiles
// Deferred per-warp row-max scratch: [cta][ht(32)][wn(2)][64 rows]
__device__ __align__(16) float g_rmax[512 * 32 * 2 * 64];

// smem: three 16KB half-tile buffers (buf2 doubles as A staging in prologue)
#define HB_OFF(b)  ((b) * 16384)
#define SMEM_BYTES (3 * 16384 + 128)

__device__ __forceinline__ uint32_t smem_u32(const void* p) {
    uint32_t a;
    asm("{ .reg .u64 t; cvta.to.shared.u64 t, %1; cvt.u32.u64 %0, t; }" : "=r"(a) : "l"(p));
    return a;
}
__device__ __forceinline__ void cp16(uint32_t sm, const void* g) {
    asm volatile("cp.async.cg.shared.global [%0], [%1], 16;" :: "r"(sm), "l"(g));
}
#define CP_COMMIT() asm volatile("cp.async.commit_group;" ::: "memory")
#define CP_WAIT(n)  asm volatile("cp.async.wait_group %0;" :: "n"(n) : "memory")

__device__ __forceinline__ void ldsm4(uint32_t& r0, uint32_t& r1, uint32_t& r2, uint32_t& r3,
                                      uint32_t addr) {
    asm volatile("ldmatrix.sync.aligned.m8n8.x4.shared.b16 {%0,%1,%2,%3}, [%4];"
                 : "=r"(r0), "=r"(r1), "=r"(r2), "=r"(r3) : "r"(addr));
}
__device__ __forceinline__ void mma16(float* d, const uint32_t* a, uint32_t b0, uint32_t b1) {
    asm volatile(
        "mma.sync.aligned.m16n8k16.row.col.f32.f16.f16.f32 "
        "{%0,%1,%2,%3}, {%4,%5,%6,%7}, {%8,%9}, {%0,%1,%2,%3};"
        : "+f"(d[0]), "+f"(d[1]), "+f"(d[2]), "+f"(d[3])
        : "r"(a[0]), "r"(a[1]), "r"(a[2]), "r"(a[3]), "r"(b0), "r"(b1));
}

// ---------------------------------------------------------------------------
// Pre-kernel: fp32 [128 x 128] tile -> fp16 swizzled (row*256B, unit^(row&7)).
// ---------------------------------------------------------------------------
extern "C" __global__ void __launch_bounds__(256)
colbert_convert(const float* __restrict__ Q, const float* __restrict__ P)
{
    const int bid = blockIdx.x, t = threadIdx.x;
    const float4* src;
    char* dst;
    if (bid < 128) { src = reinterpret_cast<const float4*>(P) + (size_t)bid * 4096; dst = g_Ph + (size_t)bid * 32768; }
    else           { src = reinterpret_cast<const float4*>(Q) + (size_t)(bid - 128) * 4096; dst = g_Qh + (size_t)(bid - 128) * 32768; }
    #pragma unroll
    for (int j = 0; j < 16; ++j) {
        int f4 = j * 256 + t;
        float4 v = src[f4];
        int row = f4 >> 5, c4 = f4 & 31;
        __half2 h0 = __floats2half2_rn(v.x, v.y);
        __half2 h1 = __floats2half2_rn(v.z, v.w);
        uint2 w;
        w.x = *reinterpret_cast<uint32_t*>(&h0);
        w.y = *reinterpret_cast<uint32_t*>(&h1);
        int off = row * 256 + ((((c4 >> 1) ^ (row & 7))) << 4) + ((c4 & 1) << 3);
        *reinterpret_cast<uint2*>(dst + off) = w;
    }
}

// ---------------------------------------------------------------------------
// Main: 512 CTAs x 128 threads, 3 CTAs/SM. CTA (mi2=bid>>3: rows [mi2*64,+64),
// cg=bid&7: 16 c's). Loop over 32 half-tiles (ht = 2c + h, 64 n-rows each).
// Warps: wm=wid>>1 (M=32), wn=wid&1 (N=32 within the half).
// ---------------------------------------------------------------------------
extern "C" __global__ void __launch_bounds__(128, 3)
colbert_fused(float* __restrict__ out)
{
    extern __shared__ __align__(128) char smem[];
    const uint32_t sbase = smem_u32(smem);

    const int t    = threadIdx.x;
    const int lane = t & 31;
    const int wid  = t >> 5;
    const int wm   = wid >> 1;
    const int wn   = wid & 1;
    const int mi2  = blockIdx.x >> 3;
    const int cg   = blockIdx.x & 7;
    const int gid  = lane >> 2;
    const int tig  = lane & 3;

    // ---- prologue: A -> HB2, ht0 -> HB0 (G0); ht1 -> HB1 (G1)
    const char* gB0 = g_Ph + (size_t)(cg * 16) * 32768;   // first half-tile of c group
    {
        const char* gA = g_Qh + (size_t)(mi2 >> 1) * 32768 + (size_t)(mi2 & 1) * 16384;
        #pragma unroll
        for (int j = 0; j < 8; ++j) {
            int off = j * 2048 + t * 16;
            cp16(sbase + HB_OFF(2) + off, gA + off);
            cp16(sbase + HB_OFF(0) + off, gB0 + off);
        }
        CP_COMMIT();                                       // G0 = {A, ht0}
        #pragma unroll
        for (int j = 0; j < 8; ++j) {
            int off = j * 2048 + t * 16;
            cp16(sbase + HB_OFF(1) + off, gB0 + 16384 + off);
        }
        CP_COMMIT();                                       // G1 = {ht1}
    }
    CP_WAIT(1);
    __syncthreads();

    // ---- A fragments -> registers (rows 0..63 from HB2 region)
    uint32_t aF[2][8][4];
    {
        const int rA = wm * 32 + (lane & 15);
        const int kqA = lane >> 4;
        #pragma unroll
        for (int mt = 0; mt < 2; ++mt) {
            const int row = rA + mt * 16;
            const uint32_t rowbase = sbase + HB_OFF(2) + row * 256;
            #pragma unroll
            for (int ks = 0; ks < 8; ++ks) {
                uint32_t addr = rowbase + (((2 * ks + kqA) ^ (row & 7)) << 4);
                ldsm4(aF[mt][ks][0], aF[mt][ks][1], aF[mt][ks][2], aF[mt][ks][3], addr);
            }
        }
    }
    __syncthreads();     // aF reads done before ht2 overwrites HB2
    {
        #pragma unroll
        for (int j = 0; j < 8; ++j) {
            int off = j * 2048 + t * 16;
            cp16(sbase + HB_OFF(2) + off, gB0 + 2 * 16384 + off);
        }
        CP_COMMIT();                                       // G2 = {ht2}
    }

    // per-thread B rows within a 64-row half (np = 0,1)
    const int rBl = (lane & 7) + ((lane >> 4) << 3);
    const int kqB = (lane >> 3) & 1;
    int rOff[2], rSw[2];
    #pragma unroll
    for (int np = 0; np < 2; ++np) {
        int row = wn * 32 + np * 16 + rBl;
        rOff[np] = row * 256;
        rSw[np]  = row & 7;
    }

    uint32_t bF[2][2][4];
    #pragma unroll
    for (int np = 0; np < 2; ++np) {
        uint32_t addr = sbase + HB_OFF(0) + rOff[np] + ((kqB ^ rSw[np]) << 4);
        ldsm4(bF[0][np][0], bF[0][np][1], bF[0][np][2], bF[0][np][3], addr);
    }

    for (int ht = 0; ht < 32; ++ht) {
        const uint32_t Bbase = sbase + HB_OFF(ht % 3);

        float acc[2][4][4];
        #pragma unroll
        for (int mt = 0; mt < 2; ++mt)
            #pragma unroll
            for (int nt = 0; nt < 4; ++nt)
                #pragma unroll
                for (int r = 0; r < 4; ++r) acc[mt][nt][r] = 0.0f;

        #pragma unroll
        for (int ks = 0; ks < 8; ++ks) {
            const int cur = ks & 1, nxt = cur ^ 1;
            if (ks < 7) {
                const int ku = 2 * (ks + 1) + kqB;
                #pragma unroll
                for (int np = 0; np < 2; ++np) {
                    uint32_t addr = Bbase + rOff[np] + ((ku ^ rSw[np]) << 4);
                    ldsm4(bF[nxt][np][0], bF[nxt][np][1], bF[nxt][np][2], bF[nxt][np][3], addr);
                }
            }
            #pragma unroll
            for (int np = 0; np < 2; ++np)
                #pragma unroll
                for (int mt = 0; mt < 2; ++mt) {
                    mma16(acc[mt][2 * np],     aF[mt][ks], bF[cur][np][0], bF[cur][np][1]);
                    mma16(acc[mt][2 * np + 1], aF[mt][ks], bF[cur][np][2], bF[cur][np][3]);
                }
        }

        // ---- boundary: recycle + next-ht bF0 prefetch
        if (ht + 1 < 32) {
            if (ht + 3 < 32) { CP_WAIT(1); } else { CP_WAIT(0); }
            __syncthreads();
            if (ht + 3 < 32) {
                const char* gB = gB0 + (size_t)(ht + 3) * 16384;
                #pragma unroll
                for (int j = 0; j < 8; ++j) {
                    int off = j * 2048 + t * 16;
                    cp16(sbase + HB_OFF(ht % 3) + off, gB + off);
                }
                CP_COMMIT();
            }
            const uint32_t Bnext = sbase + HB_OFF((ht + 1) % 3);
            #pragma unroll
            for (int np = 0; np < 2; ++np) {
                uint32_t addr = Bnext + rOff[np] + ((kqB ^ rSw[np]) << 4);
                ldsm4(bF[0][np][0], bF[0][np][1], bF[0][np][2], bF[0][np][3], addr);
            }
        }

        // ---- epilogue: per-row max over this warp's 32 n-cols -> global scratch
        float* gr = g_rmax + ((size_t)(blockIdx.x * 32 + ht) * 2 + wn) * 64;
        #pragma unroll
        for (int mt = 0; mt < 2; ++mt) {
            float m0 = acc[mt][0][0], m1 = acc[mt][0][2];
            #pragma unroll
            for (int nt = 0; nt < 4; ++nt) {
                m0 = fmaxf(m0, fmaxf(acc[mt][nt][0], acc[mt][nt][1]));
                m1 = fmaxf(m1, fmaxf(acc[mt][nt][2], acc[mt][nt][3]));
            }
            m0 = fmaxf(m0, __shfl_xor_sync(0xffffffffu, m0, 1));
            m0 = fmaxf(m0, __shfl_xor_sync(0xffffffffu, m0, 2));
            m1 = fmaxf(m1, __shfl_xor_sync(0xffffffffu, m1, 1));
            m1 = fmaxf(m1, __shfl_xor_sync(0xffffffffu, m1, 2));
            if (tig == 0) {
                gr[wm * 32 + mt * 16 + gid]     = m0;
                gr[wm * 32 + mt * 16 + 8 + gid] = m1;
            }
        }
    }

    __syncthreads();  // CTA-scope fence: all warps' g_rmax writes visible

    // ---- combine: warp w handles 4 c's; slabs [2ci:wn0,wn1][2ci+1:wn0,wn1]
    {
        const int b0 = mi2 * 2, b1 = mi2 * 2 + 1;
        #pragma unroll
        for (int cl = 0; cl < 4; ++cl) {
            const int ci = wid * 4 + cl;
            const float* r = g_rmax + (size_t)(blockIdx.x * 32 + ci * 2) * 128;
            float v0 = fmaxf(fmaxf(r[lane],      r[64 + lane]),
                             fmaxf(r[128 + lane], r[192 + lane]));
            float v1 = fmaxf(fmaxf(r[32 + lane],  r[96 + lane]),
                             fmaxf(r[160 + lane], r[224 + lane]));
            #pragma unroll
            for (int off = 16; off; off >>= 1) {
                v0 += __shfl_xor_sync(0xffffffffu, v0, off);
                v1 += __shfl_xor_sync(0xffffffffu, v1, off);
            }
            if (lane == 0) {
                const int c = cg * 16 + ci;
                g_scores[b0 * Bn + c] = v0;
                g_scores[b1 * Bn + c] = v1;
            }
        }
    }

    // ---- last CTA computes the loss
    __syncthreads();
    __threadfence();
    __shared__ unsigned s_rank;
    __shared__ float sred[32];
    if (t == 0) s_rank = atomicAdd(&g_cnt, 1);
    __syncthreads();
    if (s_rank != 511) return;
    if (t == 0) atomicExch(&g_cnt, 0);
    __threadfence();

    const float4* rp = reinterpret_cast<const float4*>(&g_scores[t * Bn]);
    float m = -CUDART_INF_F, diag = 0.0f;
    #pragma unroll
    for (int k4 = 0; k4 < 32; ++k4) {
        float4 v = rp[k4];
        m = fmaxf(m, fmaxf(fmaxf(v.x, v.y), fmaxf(v.z, v.w)));
        int cb = k4 * 4;
        if (t == cb + 0) diag = v.x;
        if (t == cb + 1) diag = v.y;
        if (t == cb + 2) diag = v.z;
        if (t == cb + 3) diag = v.w;
    }
    float s = 0.0f;
    #pragma unroll
    for (int k4 = 0; k4 < 32; ++k4) {
        float4 v = rp[k4];
        s += expf(50.0f * (v.x - m)) + expf(50.0f * (v.y - m)) +
             expf(50.0f * (v.z - m)) + expf(50.0f * (v.w - m));
    }
    float term = 50.0f * diag - (50.0f * m + logf(s));

    #pragma unroll
    for (int off = 16; off; off >>= 1) term += __shfl_xor_sync(0xffffffffu, term, off);
    if (lane == 0) sred[wid] = term;
    __syncthreads();
    if (t == 0) out[0] = -(sred[0] + sred[1] + sred[2] + sred[3]) / 128.0f;
}

// ---------------------------------------------------------------------------
extern "C" void kernel_launch(void* const* d_in, const int* in_sizes, int n_in,
                              void* d_out, int out_size)
{
    const float* Q = (const float*)d_in[0];  // [128, 32, 128]
    const float* P = (const float*)d_in[1];  // [128, 128, 128]
    float* out = (float*)d_out;

    cudaFuncSetAttribute(colbert_fused,
                         cudaFuncAttributeMaxDynamicSharedMemorySize, SMEM_BYTES);
    colbert_convert<<<160, 256>>>(Q, P);
    colbert_fused<<<512, 128, SMEM_BYTES>>>(out);
}

// round 11
// speedup vs baseline: 1.6284x; 1.1101x over previous
#include <cuda_runtime.h>
#include <cuda_fp16.h>
#include <math_constants.h>
#include <cstdint>

#define Bn 128
#define Hn 128

__device__ float    g_scores[Bn * Bn];
__device__ unsigned g_cnt = 0;
// Pre-converted, pre-swizzled fp16 tiles (tile = 128 rows x 256B swizzled)
__device__ __align__(16) char g_Qh[32 * 32768];    // 1MB: 32 mi-tiles
__device__ __align__(16) char g_Ph[128 * 32768];   // 4MB: 128 c-tiles
// Deferred per-warp row-max scratch: [cta][c][wn][64]
__device__ __align__(16) float g_rmax[256 * 32 * 2 * 64];

// smem: B buf0 (32K) | B buf1 (32K) | B buf2 (32K, A overlaid during prologue)
#define B_OFF(b)   ((b) * 32768)
#define A_OFF      65536
#define SMEM_BYTES (3 * 32768 + 128)

__device__ __forceinline__ uint32_t smem_u32(const void* p) {
    uint32_t a;
    asm("{ .reg .u64 t; cvta.to.shared.u64 t, %1; cvt.u32.u64 %0, t; }" : "=r"(a) : "l"(p));
    return a;
}
__device__ __forceinline__ void cp16(uint32_t sm, const void* g) {
    asm volatile("cp.async.cg.shared.global [%0], [%1], 16;" :: "r"(sm), "l"(g));
}
#define CP_COMMIT() asm volatile("cp.async.commit_group;" ::: "memory")
#define CP_WAIT(n)  asm volatile("cp.async.wait_group %0;" :: "n"(n) : "memory")

__device__ __forceinline__ void ldsm4(uint32_t& r0, uint32_t& r1, uint32_t& r2, uint32_t& r3,
                                      uint32_t addr) {
    asm volatile("ldmatrix.sync.aligned.m8n8.x4.shared.b16 {%0,%1,%2,%3}, [%4];"
                 : "=r"(r0), "=r"(r1), "=r"(r2), "=r"(r3) : "r"(addr));
}
// f16-accumulator MMA: D(16x8 f16, 2 regs) += A(16x16) * B(16x8)
__device__ __forceinline__ void mma16h(uint32_t* d, const uint32_t* a, uint32_t b0, uint32_t b1) {
    asm volatile(
        "mma.sync.aligned.m16n8k16.row.col.f16.f16.f16.f16 "
        "{%0,%1}, {%2,%3,%4,%5}, {%6,%7}, {%0,%1};"
        : "+r"(d[0]), "+r"(d[1])
        : "r"(a[0]), "r"(a[1]), "r"(a[2]), "r"(a[3]), "r"(b0), "r"(b1));
}
__device__ __forceinline__ uint32_t hmax2(uint32_t a, uint32_t b) {
    uint32_t r; asm("max.f16x2 %0, %1, %2;" : "=r"(r) : "r"(a), "r"(b)); return r;
}
__device__ __forceinline__ float hpair_max_f32(uint32_t p) {
    __half2 h = *reinterpret_cast<__half2*>(&p);
    return fmaxf(__half2float(__low2half(h)), __half2float(__high2half(h)));
}

// ---------------------------------------------------------------------------
// Pre-kernel: fp32 [128 x 128] tile -> fp16 swizzled (row*256B, unit^(row&7)).
// ---------------------------------------------------------------------------
extern "C" __global__ void __launch_bounds__(256)
colbert_convert(const float* __restrict__ Q, const float* __restrict__ P)
{
    const int bid = blockIdx.x, t = threadIdx.x;
    const float4* src;
    char* dst;
    if (bid < 128) { src = reinterpret_cast<const float4*>(P) + (size_t)bid * 4096; dst = g_Ph + (size_t)bid * 32768; }
    else           { src = reinterpret_cast<const float4*>(Q) + (size_t)(bid - 128) * 4096; dst = g_Qh + (size_t)(bid - 128) * 32768; }
    #pragma unroll
    for (int j = 0; j < 16; ++j) {
        int f4 = j * 256 + t;
        float4 v = src[f4];
        int row = f4 >> 5, c4 = f4 & 31;
        __half2 h0 = __floats2half2_rn(v.x, v.y);
        __half2 h1 = __floats2half2_rn(v.z, v.w);
        uint2 w;
        w.x = *reinterpret_cast<uint32_t*>(&h0);
        w.y = *reinterpret_cast<uint32_t*>(&h1);
        int off = row * 256 + ((((c4 >> 1) ^ (row & 7))) << 4) + ((c4 & 1) << 3);
        *reinterpret_cast<uint2*>(dst + off) = w;
    }
}

// ---------------------------------------------------------------------------
// Main: 256 CTAs x 128 threads, 2 CTAs/SM. CTA (mi2=bid>>2: rows [mi2*64,+64),
// cg=bid&3). Warps: wm=wid>>1 (M=32 = one b), wn=wid&1 (N=64 half).
// f16 accumulators; 3-deep cp.async B pipeline; rmax deferred to global.
// ---------------------------------------------------------------------------
extern "C" __global__ void __launch_bounds__(128, 2)
colbert_fused(float* __restrict__ out)
{
    extern __shared__ __align__(128) char smem[];
    const uint32_t sbase = smem_u32(smem);

    const int t    = threadIdx.x;
    const int lane = t & 31;
    const int wid  = t >> 5;
    const int wm   = wid >> 1;
    const int wn   = wid & 1;
    const int mi2  = blockIdx.x >> 2;
    const int cg   = blockIdx.x & 3;
    const int gid  = lane >> 2;
    const int tig  = lane & 3;

    // ---- prologue
    const char* gB0 = g_Ph + (size_t)(cg * 32) * 32768;
    {
        const char* gA = g_Qh + (size_t)(mi2 >> 1) * 32768 + (size_t)(mi2 & 1) * 16384;
        #pragma unroll
        for (int j = 0; j < 8; ++j) {
            int off = j * 2048 + t * 16;
            cp16(sbase + A_OFF + off, gA + off);
        }
        #pragma unroll
        for (int j = 0; j < 16; ++j) {
            int off = j * 2048 + t * 16;
            cp16(sbase + B_OFF(0) + off, gB0 + off);
        }
        CP_COMMIT();                            // G0 = {A, tile0}
        #pragma unroll
        for (int j = 0; j < 16; ++j) {
            int off = j * 2048 + t * 16;
            cp16(sbase + B_OFF(1) + off, gB0 + 32768 + off);
        }
        CP_COMMIT();                            // G1 = {tile1}
    }
    CP_WAIT(1);
    __syncthreads();

    // ---- A fragments -> registers (from buf2 region, before tile2 lands)
    uint32_t aF[2][8][4];
    {
        const int rA = wm * 32 + (lane & 15);
        const int kqA = lane >> 4;
        #pragma unroll
        for (int mt = 0; mt < 2; ++mt) {
            const int row = rA + mt * 16;
            const uint32_t rowbase = sbase + A_OFF + row * 256;
            #pragma unroll
            for (int ks = 0; ks < 8; ++ks) {
                uint32_t addr = rowbase + (((2 * ks + kqA) ^ (row & 7)) << 4);
                ldsm4(aF[mt][ks][0], aF[mt][ks][1], aF[mt][ks][2], aF[mt][ks][3], addr);
            }
        }
    }
    __syncthreads();     // aF reads done before tile2 overwrites A region
    {
        #pragma unroll
        for (int j = 0; j < 16; ++j) {
            int off = j * 2048 + t * 16;
            cp16(sbase + B_OFF(2) + off, gB0 + 2 * 32768 + off);
        }
        CP_COMMIT();                            // G2 = {tile2}
    }

    const int rBl = (lane & 7) + ((lane >> 4) << 3);
    const int kqB = (lane >> 3) & 1;
    int rOff[4], rSw[4];
    #pragma unroll
    for (int np = 0; np < 4; ++np) {
        int row = wn * 64 + np * 16 + rBl;
        rOff[np] = row * 256;
        rSw[np]  = row & 7;
    }

    uint32_t bF[2][4][4];
    #pragma unroll
    for (int np = 0; np < 4; ++np) {
        uint32_t addr = sbase + B_OFF(0) + rOff[np] + ((kqB ^ rSw[np]) << 4);
        ldsm4(bF[0][np][0], bF[0][np][1], bF[0][np][2], bF[0][np][3], addr);
    }

    for (int i = 0; i < 32; ++i) {
        const uint32_t Bbase = sbase + B_OFF(i % 3);

        uint32_t acc[2][8][2];   // f16x2 accumulators
        #pragma unroll
        for (int mt = 0; mt < 2; ++mt)
            #pragma unroll
            for (int nt = 0; nt < 8; ++nt) { acc[mt][nt][0] = 0u; acc[mt][nt][1] = 0u; }

        #pragma unroll
        for (int ks = 0; ks < 8; ++ks) {
            const int cur = ks & 1, nxt = cur ^ 1;
            if (ks < 7) {
                const int ku = 2 * (ks + 1) + kqB;
                #pragma unroll
                for (int np = 0; np < 4; ++np) {
                    uint32_t addr = Bbase + rOff[np] + ((ku ^ rSw[np]) << 4);
                    ldsm4(bF[nxt][np][0], bF[nxt][np][1], bF[nxt][np][2], bF[nxt][np][3], addr);
                }
            }
            #pragma unroll
            for (int np = 0; np < 4; ++np)
                #pragma unroll
                for (int mt = 0; mt < 2; ++mt) {
                    mma16h(acc[mt][2 * np],     aF[mt][ks], bF[cur][np][0], bF[cur][np][1]);
                    mma16h(acc[mt][2 * np + 1], aF[mt][ks], bF[cur][np][2], bF[cur][np][3]);
                }
        }

        // ---- boundary: zero-wait recycle + next-iter bF0 prefetch
        if (i + 1 < 32) {
            if (i + 3 < 32) { CP_WAIT(1); } else { CP_WAIT(0); }
            __syncthreads();
            if (i + 3 < 32) {
                const char* gB = gB0 + (size_t)(i + 3) * 32768;
                #pragma unroll
                for (int j = 0; j < 16; ++j) {
                    int off = j * 2048 + t * 16;
                    cp16(sbase + B_OFF(i % 3) + off, gB + off);
                }
                CP_COMMIT();
            }
            const uint32_t Bnext = sbase + B_OFF((i + 1) % 3);
            #pragma unroll
            for (int np = 0; np < 4; ++np) {
                uint32_t addr = Bnext + rOff[np] + ((kqB ^ rSw[np]) << 4);
                ldsm4(bF[0][np][0], bF[0][np][1], bF[0][np][2], bF[0][np][3], addr);
            }
        }

        // ---- epilogue: packed f16 row-max over 64 n-cols -> global scratch
        float* gr = g_rmax + ((size_t)(blockIdx.x * 32 + i) * 2 + wn) * 64;
        #pragma unroll
        for (int mt = 0; mt < 2; ++mt) {
            uint32_t p0 = acc[mt][0][0], p1 = acc[mt][0][1];
            #pragma unroll
            for (int nt = 1; nt < 8; ++nt) {
                p0 = hmax2(p0, acc[mt][nt][0]);
                p1 = hmax2(p1, acc[mt][nt][1]);
            }
            float m0 = hpair_max_f32(p0);
            float m1 = hpair_max_f32(p1);
            m0 = fmaxf(m0, __shfl_xor_sync(0xffffffffu, m0, 1));
            m0 = fmaxf(m0, __shfl_xor_sync(0xffffffffu, m0, 2));
            m1 = fmaxf(m1, __shfl_xor_sync(0xffffffffu, m1, 1));
            m1 = fmaxf(m1, __shfl_xor_sync(0xffffffffu, m1, 2));
            if (tig == 0) {
                gr[wm * 32 + mt * 16 + gid]     = m0;
                gr[wm * 32 + mt * 16 + 8 + gid] = m1;
            }
        }
    }

    __syncthreads();  // CTA-scope fence: all warps' g_rmax writes visible

    // ---- combine: warp w handles 8 c's; lane = s-row within each b
    {
        const int b0 = mi2 * 2, b1 = mi2 * 2 + 1;
        #pragma unroll
        for (int cl = 0; cl < 8; ++cl) {
            const int ci = wid * 8 + cl;
            const float* r = g_rmax + (size_t)(blockIdx.x * 32 + ci) * 128;
            float v0 = fmaxf(r[lane],      r[64 + lane]);
            float v1 = fmaxf(r[32 + lane], r[96 + lane]);
            #pragma unroll
            for (int off = 16; off; off >>= 1) {
                v0 += __shfl_xor_sync(0xffffffffu, v0, off);
                v1 += __shfl_xor_sync(0xffffffffu, v1, off);
            }
            if (lane == 0) {
                const int c = cg * 32 + ci;
                g_scores[b0 * Bn + c] = v0;
                g_scores[b1 * Bn + c] = v1;
            }
        }
    }

    // ---- last CTA computes the loss
    __syncthreads();
    __threadfence();
    __shared__ unsigned s_rank;
    __shared__ float sred[32];
    if (t == 0) s_rank = atomicAdd(&g_cnt, 1);
    __syncthreads();
    if (s_rank != 255) return;
    if (t == 0) atomicExch(&g_cnt, 0);
    __threadfence();

    const float4* rp = reinterpret_cast<const float4*>(&g_scores[t * Bn]);
    float m = -CUDART_INF_F, diag = 0.0f;
    #pragma unroll
    for (int k4 = 0; k4 < 32; ++k4) {
        float4 v = rp[k4];
        m = fmaxf(m, fmaxf(fmaxf(v.x, v.y), fmaxf(v.z, v.w)));
        int cb = k4 * 4;
        if (t == cb + 0) diag = v.x;
        if (t == cb + 1) diag = v.y;
        if (t == cb + 2) diag = v.z;
        if (t == cb + 3) diag = v.w;
    }
    float s = 0.0f;
    #pragma unroll
    for (int k4 = 0; k4 < 32; ++k4) {
        float4 v = rp[k4];
        s += expf(50.0f * (v.x - m)) + expf(50.0f * (v.y - m)) +
             expf(50.0f * (v.z - m)) + expf(50.0f * (v.w - m));
    }
    float term = 50.0f * diag - (50.0f * m + logf(s));

    #pragma unroll
    for (int off = 16; off; off >>= 1) term += __shfl_xor_sync(0xffffffffu, term, off);
    if (lane == 0) sred[wid] = term;
    __syncthreads();
    if (t == 0) out[0] = -(sred[0] + sred[1] + sred[2] + sred[3]) / 128.0f;
}

// ---------------------------------------------------------------------------
extern "C" void kernel_launch(void* const* d_in, const int* in_sizes, int n_in,
                              void* d_out, int out_size)
{
    const float* Q = (const float*)d_in[0];  // [128, 32, 128]
    const float* P = (const float*)d_in[1];  // [128, 128, 128]
    float* out = (float*)d_out;

    cudaFuncSetAttribute(colbert_fused,
                         cudaFuncAttributeMaxDynamicSharedMemorySize, SMEM_BYTES);
    colbert_convert<<<160, 256>>>(Q, P);
    colbert_fused<<<256, 128, SMEM_BYTES>>>(out);
}